// round 2
// baseline (speedup 1.0000x reference)
#include <cuda_runtime.h>
#include <cuda_bf16.h>
#include <cstdint>

// ---------------- problem constants ----------------
#define BATCH     4
#define SEQLEN    4096
#define NTOK      (BATCH * SEQLEN)      // 16384
#define DMODEL    1024
#define EVDIM     16
#define DIN       2048                  // d_inner
#define NHEADS    32
#define DSTATE    64
#define HEADDIM   64
#define DCONV     4
#define BLK       16                    // block_len
#define NCHUNK    (SEQLEN / BLK)        // 256

// ---------------- scratch (device globals; no runtime allocation) ----------
__device__ float g_xz [ (size_t)NTOK * 2 * DIN ];   // 16384 x 4096  (x_path | z)
__device__ float g_xc [ (size_t)NTOK * DIN ];       // 16384 x 2048
__device__ float g_A  [ (size_t)NTOK * NHEADS ];    // 16384 x 32
__device__ float g_B  [ (size_t)NTOK * DIN ];       // 16384 x 2048 (B_ssm)
__device__ float g_C  [ (size_t)NTOK * DIN ];       // 16384 x 2048 (C_ssm)
__device__ float g_Y  [ (size_t)NTOK * DIN ];       // 16384 x 2048
__device__ float g_out[ (size_t)NTOK * DMODEL ];    // 16384 x 1024 (pre-LN)

// ---------------- tiled SGEMM ----------------
// C[M,N] = A[M,K] @ W[K,N], fp32. BM=BN=128, BK=16, 8x8 microtile, 256 threads.
// MODE 0: A = concat(x[.,1024], ev[.,16])       (K = 1040)
// MODE 1: A = g_xc                              (K = 2048)
// MODE 2: A = g_Y * silu(z), z = g_xz[:,2048:]  (K = 2048)
// OUT  0: g_xz   1: g_B   2: g_C   3: g_out
#define BM 128
#define BN 128
#define BKK 16

__device__ __forceinline__ float silu_f(float z) {
    return z / (1.f + __expf(-z));
}

template<int MODE, int OUT>
__global__ void __launch_bounds__(256)
sgemm_kernel(const float* __restrict__ X0, const float* __restrict__ X1,
             const float* __restrict__ W, int M, int N, int K)
{
    __shared__ float As[BKK][BM];
    __shared__ float Bs[BKK][BN + 4];

    const int tid = threadIdx.x;
    const int row0 = blockIdx.y * BM;
    const int col0 = blockIdx.x * BN;
    const int tx = tid & 15;        // 0..15  -> N
    const int ty = tid >> 4;        // 0..15  -> M

    float acc[8][8];
#pragma unroll
    for (int i = 0; i < 8; i++)
#pragma unroll
        for (int j = 0; j < 8; j++) acc[i][j] = 0.f;

    for (int k0 = 0; k0 < K; k0 += BKK) {
        // ---- load A tile (128 x 16), store transposed As[k][m]
#pragma unroll
        for (int u = 0; u < 2; u++) {
            int f  = tid + u * 256;           // 0..511 float4s
            int ar = f >> 2;                  // row in tile 0..127
            int ak = (f & 3) * 4;             // k within tile
            size_t m = (size_t)(row0 + ar);
            int k = k0 + ak;
            float4 v;
            if (MODE == 0) {
                if (k < DMODEL) v = *(const float4*)(X0 + m * DMODEL + k);
                else            v = *(const float4*)(X1 + m * EVDIM + (k - DMODEL));
            } else if (MODE == 1) {
                v = *(const float4*)(g_xc + m * (size_t)DIN + k);
            } else {
                float4 y = *(const float4*)(g_Y  + m * (size_t)DIN + k);
                float4 z = *(const float4*)(g_xz + m * (size_t)(2*DIN) + DIN + k);
                v.x = y.x * silu_f(z.x);
                v.y = y.y * silu_f(z.y);
                v.z = y.z * silu_f(z.z);
                v.w = y.w * silu_f(z.w);
            }
            As[ak + 0][ar] = v.x;
            As[ak + 1][ar] = v.y;
            As[ak + 2][ar] = v.z;
            As[ak + 3][ar] = v.w;
        }
        // ---- load B tile (16 x 128)
#pragma unroll
        for (int u = 0; u < 2; u++) {
            int f  = tid + u * 256;
            int br = f >> 5;                  // 0..15
            int bc = (f & 31) * 4;            // 0..124
            float4 v = *(const float4*)(W + (size_t)(k0 + br) * N + col0 + bc);
            *(float4*)(&Bs[br][bc]) = v;
        }
        __syncthreads();

#pragma unroll
        for (int kk = 0; kk < BKK; kk++) {
            float ra[8], rb[8];
#pragma unroll
            for (int i = 0; i < 8; i++) ra[i] = As[kk][ty * 8 + i];
#pragma unroll
            for (int j = 0; j < 8; j++) rb[j] = Bs[kk][tx * 8 + j];
#pragma unroll
            for (int i = 0; i < 8; i++)
#pragma unroll
                for (int j = 0; j < 8; j++)
                    acc[i][j] += ra[i] * rb[j];
        }
        __syncthreads();
    }

    float* Cm = (OUT == 0) ? g_xz : (OUT == 1) ? g_B : (OUT == 2) ? g_C : g_out;
#pragma unroll
    for (int i = 0; i < 8; i++) {
        size_t m = (size_t)(row0 + ty * 8 + i);
        float* cp = Cm + m * N + col0 + tx * 8;
        *(float4*)(cp)     = make_float4(acc[i][0], acc[i][1], acc[i][2], acc[i][3]);
        *(float4*)(cp + 4) = make_float4(acc[i][4], acc[i][5], acc[i][6], acc[i][7]);
    }
}

// ---------------- causal depthwise conv (d_conv=4) + SiLU ----------------
__global__ void __launch_bounds__(256)
conv_silu_kernel(const float* __restrict__ cw, const float* __restrict__ cb)
{
    long long idx = (long long)blockIdx.x * blockDim.x + threadIdx.x;
    if (idx >= (long long)NTOK * DIN) return;
    int ch = (int)(idx & (DIN - 1));
    long long tok = idx >> 11;                 // token index (b*4096 + l)
    int l = (int)(tok & (SEQLEN - 1));
    long long tok0 = tok - l;                  // batch base token

    float acc = cb[ch];
#pragma unroll
    for (int j = 0; j < DCONV; j++) {
        int ls = l - (DCONV - 1) + j;
        if (ls >= 0)
            acc += cw[ch * DCONV + j] * g_xz[(tok0 + ls) * (size_t)(2*DIN) + ch];
    }
    g_xc[idx] = silu_f(acc);
}

// ---------------- dt projection -> softplus -> A = -exp(A_log)*dt ----------
// M=16384, N=32, K=2048. 32 tokens per block, 256 threads (thread = (tokgrp, head))
__global__ void __launch_bounds__(256)
dtA_kernel(const float* __restrict__ w, const float* __restrict__ dtb,
           const float* __restrict__ Alog)
{
    __shared__ float sw[64][33];
    __shared__ float sx[32][65];
    const int t = threadIdx.x;
    const int tok0 = blockIdx.x * 32;
    const int h  = t & 31;
    const int tr = t >> 5;              // 0..7, owns tokens tr*4 .. tr*4+3

    float acc[4] = {0.f, 0.f, 0.f, 0.f};
    for (int k0 = 0; k0 < DIN; k0 += 64) {
#pragma unroll
        for (int u = 0; u < 8; u++) {
            int f = t + u * 256;
            int kk = f >> 5, hh = f & 31;
            sw[kk][hh] = w[(size_t)(k0 + kk) * NHEADS + hh];
        }
#pragma unroll
        for (int u = 0; u < 8; u++) {
            int f = t + u * 256;
            int tk = f >> 6, kk = f & 63;
            sx[tk][kk] = g_xc[(size_t)(tok0 + tk) * DIN + k0 + kk];
        }
        __syncthreads();
#pragma unroll
        for (int kk = 0; kk < 64; kk++) {
            float wv = sw[kk][h];
#pragma unroll
            for (int r = 0; r < 4; r++)
                acc[r] += sx[tr * 4 + r][kk] * wv;
        }
        __syncthreads();
    }
    float na = -__expf(Alog[h]);
    float bh = dtb[h];
#pragma unroll
    for (int r = 0; r < 4; r++) {
        float v = acc[r] + bh;
        float sp = (v > 20.f) ? v : log1pf(__expf(v));
        g_A[(size_t)(tok0 + tr * 4 + r) * NHEADS + h] = na * sp;
    }
}

// ---------------- fused SSD scan ----------------
// grid: (b*h = 128, psplit = 2), 128 threads/block.
// thread t: p = p0 + (t&31), owns state rows n = (t>>5)*16 .. +16 (16 regs).
__global__ void __launch_bounds__(128)
scan_kernel()
{
    __shared__ float sB[16][68];
    __shared__ float sC[16][68];
    __shared__ float sX[16][36];
    __shared__ float sG[16][16];
    __shared__ float sAv[16];
    __shared__ float sCum[16];
    __shared__ float sPart[16 * 4 * 32];

    const int t  = threadIdx.x;
    const int bh = blockIdx.x;
    const int bi = bh >> 5, h = bh & 31;
    const int p0 = blockIdx.y * 32;
    const int p  = t & 31;
    const int ng = t >> 5;              // 0..3
    const int i4 = ng * 4;              // this thread finalizes rows i4..i4+3
    const size_t headoff = (size_t)h * HEADDIM;

    float H[16];
#pragma unroll
    for (int i = 0; i < 16; i++) H[i] = 0.f;

    for (int c = 0; c < NCHUNK; c++) {
        const size_t l0 = (size_t)bi * SEQLEN + c * BLK;
        const size_t base = (l0 * NHEADS + h) * DSTATE;   // B/C [l0][h][0]

        // load B, C (16 x 64 each)
#pragma unroll
        for (int u = 0; u < 2; u++) {
            int f = t + u * 128;
            int r = f >> 4, q = (f & 15) * 4;
            *(float4*)&sB[r][q] = *(const float4*)(g_B + base + (size_t)r * DIN + q);
            *(float4*)&sC[r][q] = *(const float4*)(g_C + base + (size_t)r * DIN + q);
        }
        // load X p-slice (16 x 32)
        {
            int r = t >> 3, q = (t & 7) * 4;
            *(float4*)&sX[r][q] =
                *(const float4*)(g_xc + (l0 + r) * (size_t)DIN + headoff + p0 + q);
        }
        if (t < 16) sAv[t] = g_A[(l0 + t) * NHEADS + h];
        __syncthreads();

        if (t < 16) {
            float s = 0.f;
            for (int k = 0; k <= t; k++) s += sAv[k];
            sCum[t] = s;
        }
        __syncthreads();
        const float cum15 = sCum[15];

        // G[i][j] = (C_i . B_j) * exp(cum_i - cum_j) for j<=i
#pragma unroll
        for (int u = 0; u < 2; u++) {
            int e = t + u * 128;
            int i = e >> 4, j = e & 15;
            float g = 0.f;
            if (j <= i) {
                float d = 0.f;
#pragma unroll
                for (int n = 0; n < 64; n++) d += sC[i][n] * sB[j][n];
                g = d * __expf(sCum[i] - sCum[j]);
            }
            sG[i][j] = g;
        }
        // Y_off partials: for my n-range, part[i] = sum_n C[i][n]*H[n][p]
        {
            int nb = ng * 16;
#pragma unroll
            for (int i = 0; i < 16; i++) {
                float s = 0.f;
#pragma unroll
                for (int k = 0; k < 16; k++) s += sC[i][nb + k] * H[k];
                sPart[(i * 4 + ng) * 32 + p] = s;
            }
        }
        __syncthreads();

        // Y = Y_diag + exp(cum_i)*Y_off
        float yv[4];
#pragma unroll
        for (int r = 0; r < 4; r++) {
            int i = i4 + r;
            float s = 0.f;
#pragma unroll
            for (int j = 0; j < 16; j++) s += sG[i][j] * sX[j][p];
            float off = sPart[(i * 4 + 0) * 32 + p] + sPart[(i * 4 + 1) * 32 + p]
                      + sPart[(i * 4 + 2) * 32 + p] + sPart[(i * 4 + 3) * 32 + p];
            yv[r] = s + __expf(sCum[i]) * off;
        }
        __syncthreads();   // all Y_diag reads of sX done before in-place scale

        // scale X rows by decay_states, write Y
#pragma unroll
        for (int r = 0; r < 4; r++) {
            int i = i4 + r;
            sX[i][p] *= __expf(cum15 - sCum[i]);
            g_Y[(l0 + i) * (size_t)DIN + headoff + p0 + p] = yv[r];
        }
        __syncthreads();

        // H <- exp(cum15)*H + B^T (decay*X)
        {
            float eA = __expf(cum15);
            int nb = ng * 16;
#pragma unroll
            for (int k = 0; k < 16; k++) {
                float s = 0.f;
#pragma unroll
                for (int i = 0; i < 16; i++) s += sB[i][nb + k] * sX[i][p];
                H[k] = eA * H[k] + s;
            }
        }
        __syncthreads();   // before next chunk overwrites shared
    }
}

// ---------------- residual + LayerNorm ----------------
__global__ void __launch_bounds__(256)
ln_kernel(const float* __restrict__ res, const float* __restrict__ gamma,
          const float* __restrict__ beta, float* __restrict__ dout)
{
    const int row = blockIdx.x;
    const int t = threadIdx.x;
    const size_t base = (size_t)row * DMODEL;

    float4 r4 = *(const float4*)(res   + base + t * 4);
    float4 o4 = *(const float4*)(g_out + base + t * 4);
    float h0 = r4.x + o4.x, h1 = r4.y + o4.y, h2 = r4.z + o4.z, h3 = r4.w + o4.w;
    float s  = h0 + h1 + h2 + h3;
    float sq = h0*h0 + h1*h1 + h2*h2 + h3*h3;

    __shared__ float red[2][8];
#pragma unroll
    for (int o = 16; o > 0; o >>= 1) {
        s  += __shfl_xor_sync(0xffffffffu, s,  o);
        sq += __shfl_xor_sync(0xffffffffu, sq, o);
    }
    int wid = t >> 5, lid = t & 31;
    if (lid == 0) { red[0][wid] = s; red[1][wid] = sq; }
    __syncthreads();
    if (t < 32) {
        s  = (t < 8) ? red[0][t] : 0.f;
        sq = (t < 8) ? red[1][t] : 0.f;
#pragma unroll
        for (int o = 4; o > 0; o >>= 1) {
            s  += __shfl_xor_sync(0xffffffffu, s,  o);
            sq += __shfl_xor_sync(0xffffffffu, sq, o);
        }
        if (t == 0) { red[0][0] = s; red[1][0] = sq; }
    }
    __syncthreads();
    float mu  = red[0][0] * (1.f / DMODEL);
    float var = red[1][0] * (1.f / DMODEL) - mu * mu;
    float inv = rsqrtf(var + 1e-5f);

    float4 g4 = *(const float4*)(gamma + t * 4);
    float4 b4 = *(const float4*)(beta  + t * 4);
    float4 ov;
    ov.x = (h0 - mu) * inv * g4.x + b4.x;
    ov.y = (h1 - mu) * inv * g4.y + b4.y;
    ov.z = (h2 - mu) * inv * g4.z + b4.z;
    ov.w = (h3 - mu) * inv * g4.w + b4.w;
    *(float4*)(dout + base + t * 4) = ov;
}

// ---------------- launcher ----------------
extern "C" void kernel_launch(void* const* d_in, const int* in_sizes, int n_in,
                              void* d_out, int out_size)
{
    const float* x        = (const float*)d_in[0];   // (4,4096,1024)
    const float* ev       = (const float*)d_in[1];   // (4,4096,16)
    const float* w_in     = (const float*)d_in[2];   // (1040,4096)
    const float* conv_w   = (const float*)d_in[3];   // (2048,1,4)
    const float* conv_b   = (const float*)d_in[4];   // (2048,)
    const float* A_log    = (const float*)d_in[5];   // (32,)
    const float* w_B      = (const float*)d_in[6];   // (2048,2048)
    const float* w_C      = (const float*)d_in[7];   // (2048,2048)
    const float* w_dt     = (const float*)d_in[8];   // (2048,32)
    const float* b_dt     = (const float*)d_in[9];   // (32,)
    const float* w_out    = (const float*)d_in[10];  // (2048,1024)
    const float* ln_gamma = (const float*)d_in[11];  // (1024,)
    const float* ln_beta  = (const float*)d_in[12];  // (1024,)
    float* out = (float*)d_out;

    // 1) xz = [x | ev] @ w_in   (16384 x 4096)
    sgemm_kernel<0, 0><<<dim3(2 * DIN / BN, NTOK / BM), 256>>>(x, ev, w_in,
                                                               NTOK, 2 * DIN, DMODEL + EVDIM);
    // 2) xc = silu(causal_conv(x_path) + b)
    {
        long long n = (long long)NTOK * DIN;
        conv_silu_kernel<<<(unsigned)((n + 255) / 256), 256>>>(conv_w, conv_b);
    }
    // 3) A = -exp(A_log) * softplus(xc @ w_dt + b_dt)
    dtA_kernel<<<NTOK / 32, 256>>>(w_dt, b_dt, A_log);
    // 4) B_ssm, C_ssm
    sgemm_kernel<1, 1><<<dim3(DIN / BN, NTOK / BM), 256>>>(nullptr, nullptr, w_B,
                                                           NTOK, DIN, DIN);
    sgemm_kernel<1, 2><<<dim3(DIN / BN, NTOK / BM), 256>>>(nullptr, nullptr, w_C,
                                                           NTOK, DIN, DIN);
    // 5) SSD scan -> Y
    scan_kernel<<<dim3(BATCH * NHEADS, 2), 128>>>();
    // 6) out_raw = (Y * silu(z)) @ w_out
    sgemm_kernel<2, 3><<<dim3(DMODEL / BN, NTOK / BM), 256>>>(nullptr, nullptr, w_out,
                                                              NTOK, DMODEL, DIN);
    // 7) LayerNorm(residual + out_raw)
    ln_kernel<<<NTOK, 256>>>(x, ln_gamma, ln_beta, out);
}

// round 4
// speedup vs baseline: 2.2563x; 2.2563x over previous
#include <cuda_runtime.h>
#include <cuda_bf16.h>
#include <cstdint>

// ---------------- problem constants ----------------
#define BATCH     4
#define SEQLEN    4096
#define NTOK      (BATCH * SEQLEN)      // 16384
#define DMODEL    1024
#define EVDIM     16
#define DIN       2048                  // d_inner
#define NHEADS    32
#define DSTATE    64
#define HEADDIM   64
#define DCONV     4
#define BLK       16                    // block_len
#define NCHUNK    (SEQLEN / BLK)        // 256
#define KAUG      1056                  // 1040 padded to multiple of 32

// ---------------- scratch (device globals; no runtime allocation) ----------
__device__ float g_aug [ (size_t)NTOK * KAUG ];     // [x | ev | 0pad]
__device__ float g_wint[ (size_t)4096 * KAUG ];     // in_proj_w^T (padded K)
__device__ float g_wbct[ (size_t)4096 * DIN ];      // [w_B^T ; w_C^T]
__device__ float g_wot [ (size_t)DMODEL * DIN ];    // out_proj_w^T
__device__ float g_xz  [ (size_t)NTOK * 2 * DIN ];  // 16384 x 4096 (x_path | z)
__device__ float g_xc  [ (size_t)NTOK * DIN ];      // conv+silu output
__device__ float g_A   [ (size_t)NTOK * NHEADS ];
__device__ float g_BC  [ (size_t)NTOK * 2 * DIN ];  // [B(2048) | C(2048)] per row
__device__ float g_Yz  [ (size_t)NTOK * DIN ];      // Y * silu(z)
__device__ float g_out [ (size_t)NTOK * DMODEL ];   // pre-LN

// ================= helpers =================================================
__device__ __forceinline__ uint32_t smem_u32(const void* p) {
    uint32_t a;
    asm("{ .reg .u64 t; cvta.to.shared.u64 t, %1; cvt.u32.u64 %0, t; }"
        : "=r"(a) : "l"(p));
    return a;
}
__device__ __forceinline__ void cp16(uint32_t s, const void* g) {
    asm volatile("cp.async.cg.shared.global [%0], [%1], 16;\n" :: "r"(s), "l"(g));
}
__device__ __forceinline__ void cp_commit() { asm volatile("cp.async.commit_group;\n" ::); }
template<int N> __device__ __forceinline__ void cp_wait() {
    asm volatile("cp.async.wait_group %0;\n" :: "n"(N));
}
__device__ __forceinline__ uint32_t tf32r(float x) {
    uint32_t o;
    asm("cvt.rna.tf32.f32 %0, %1;" : "=r"(o) : "f"(x));
    return o;
}
__device__ __forceinline__ void mma8(float* c, const uint32_t* a, const uint32_t* b) {
    asm volatile(
        "mma.sync.aligned.m16n8k8.row.col.f32.tf32.tf32.f32 "
        "{%0,%1,%2,%3}, {%4,%5,%6,%7}, {%8,%9}, {%0,%1,%2,%3};"
        : "+f"(c[0]), "+f"(c[1]), "+f"(c[2]), "+f"(c[3])
        : "r"(a[0]), "r"(a[1]), "r"(a[2]), "r"(a[3]), "r"(b[0]), "r"(b[1]));
}
__device__ __forceinline__ float silu_f(float z) { return z / (1.f + __expf(-z)); }

// ================= tf32 warp-MMA GEMM ======================================
// C[M,Ncols] (row-major) = A[M,Kp] @ Bt[Ncols,Kp]^T.  Both operands K-major.
// Block tile 128x128xBK32, 8 warps (2 M x 4 N), warp tile 64x32, m16n8k8.
#define BM 128
#define BN 128
#define GBK 32
#define KPAD 36
#define ASZ (BM * KPAD)                  // 4608 floats (A tile, padded)
#define STAGEF (2 * ASZ)                 // A+B floats per stage = 9216
#define GEMM_SMEM (2 * STAGEF * 4)       // 73728 bytes (double buffered)

__global__ void __launch_bounds__(256, 1)
mma_gemm(const float* __restrict__ A, const float* __restrict__ Bt,
         float* __restrict__ C, int Kp, int NKB, int Ncols)
{
    extern __shared__ float sm[];
    const uint32_t sbase = smem_u32(sm);
    const int tid  = threadIdx.x;
    const int lane = tid & 31, wid = tid >> 5;
    const int mwarp = wid & 1, nwarp = wid >> 1;      // 2 x 4 warp grid
    const int g = lane >> 2, tig = lane & 3;
    const int row0 = blockIdx.y * BM, col0 = blockIdx.x * BN;

    float acc[4][4][4];
#pragma unroll
    for (int mi = 0; mi < 4; mi++)
#pragma unroll
        for (int ni = 0; ni < 4; ni++)
#pragma unroll
            for (int r = 0; r < 4; r++) acc[mi][ni][r] = 0.f;

    // ---- async fill of stage s with K-block kb (A:128x32, B:128x32)
    auto fill = [&](int kb, int s) {
        const uint32_t ab = sbase + (uint32_t)s * STAGEF * 4;
        const uint32_t bb = ab + ASZ * 4;
        const int k0 = kb * GBK;
#pragma unroll
        for (int u = 0; u < 4; u++) {
            int c = tid + u * 256;                    // 0..1023
            int r = c >> 3, kq = c & 7;               // row, 16B chunk
            cp16(ab + r * (KPAD * 4) + kq * 16,
                 A + (size_t)(row0 + r) * Kp + k0 + kq * 4);
            cp16(bb + r * (KPAD * 4) + kq * 16,
                 Bt + (size_t)(col0 + r) * Kp + k0 + kq * 4);
        }
        cp_commit();
    };

    fill(0, 0);
    for (int kb = 0; kb < NKB; kb++) {
        cp_wait<0>();
        __syncthreads();
        if (kb + 1 < NKB) fill(kb + 1, (kb + 1) & 1);

        const float* As = sm + (kb & 1) * STAGEF;
        const float* Bs = As + ASZ;
#pragma unroll
        for (int kk = 0; kk < 4; kk++) {
            const int kbase = kk * 8;
            uint32_t af[4][4], bf[4][2];
#pragma unroll
            for (int mi = 0; mi < 4; mi++) {
                const float* ap = As + (mwarp * 64 + mi * 16 + g) * KPAD + kbase + tig;
                af[mi][0] = tf32r(ap[0]);
                af[mi][1] = tf32r(ap[8 * KPAD]);
                af[mi][2] = tf32r(ap[4]);
                af[mi][3] = tf32r(ap[8 * KPAD + 4]);
            }
#pragma unroll
            for (int ni = 0; ni < 4; ni++) {
                const float* bp = Bs + (nwarp * 32 + ni * 8 + g) * KPAD + kbase + tig;
                bf[ni][0] = tf32r(bp[0]);
                bf[ni][1] = tf32r(bp[4]);
            }
#pragma unroll
            for (int mi = 0; mi < 4; mi++)
#pragma unroll
                for (int ni = 0; ni < 4; ni++)
                    mma8(acc[mi][ni], af[mi], bf[ni]);
        }
        __syncthreads();
    }

    // ---- epilogue: direct global stores (float2 per frag half)
#pragma unroll
    for (int mi = 0; mi < 4; mi++) {
        const int r0 = row0 + mwarp * 64 + mi * 16 + g;
#pragma unroll
        for (int ni = 0; ni < 4; ni++) {
            const int cc = col0 + nwarp * 32 + ni * 8 + 2 * tig;
            *(float2*)(C + (size_t)r0 * Ncols + cc) =
                make_float2(acc[mi][ni][0], acc[mi][ni][1]);
            *(float2*)(C + (size_t)(r0 + 8) * Ncols + cc) =
                make_float2(acc[mi][ni][2], acc[mi][ni][3]);
        }
    }
}

// ================= pre/post processing kernels =============================
__global__ void __launch_bounds__(256)
pack_aug_kernel(const float* __restrict__ x, const float* __restrict__ ev)
{
    long long idx = (long long)blockIdx.x * blockDim.x + threadIdx.x;
    if (idx >= (long long)NTOK * KAUG) return;
    int col = (int)(idx % KAUG);
    long long m = idx / KAUG;
    float v;
    if (col < DMODEL)                v = x[m * DMODEL + col];
    else if (col < DMODEL + EVDIM)   v = ev[m * EVDIM + (col - DMODEL)];
    else                             v = 0.f;
    g_aug[idx] = v;
}

// dst[n][kp] = (kp < K) ? src[kp*N + n] : 0
__global__ void __launch_bounds__(256)
transpose_kernel(const float* __restrict__ src, float* __restrict__ dst,
                 int K, int N, int Kp)
{
    __shared__ float tile[32][33];
    const int tx = threadIdx.x & 31, ty = threadIdx.x >> 5;
    const int kb = blockIdx.x * 32, nb = blockIdx.y * 32;
#pragma unroll
    for (int u = 0; u < 4; u++) {
        int kk = kb + ty + u * 8;
        tile[ty + u * 8][tx] = (kk < K) ? src[(size_t)kk * N + nb + tx] : 0.f;
    }
    __syncthreads();
#pragma unroll
    for (int u = 0; u < 4; u++) {
        int n = nb + ty + u * 8;
        dst[(size_t)n * Kp + kb + tx] = tile[tx][ty + u * 8];
    }
}

// causal depthwise conv (d_conv=4) + SiLU
__global__ void __launch_bounds__(256)
conv_silu_kernel(const float* __restrict__ cw, const float* __restrict__ cb)
{
    long long idx = (long long)blockIdx.x * blockDim.x + threadIdx.x;
    if (idx >= (long long)NTOK * DIN) return;
    int ch = (int)(idx & (DIN - 1));
    long long tok = idx >> 11;
    int l = (int)(tok & (SEQLEN - 1));
    long long tok0 = tok - l;
    float acc = cb[ch];
#pragma unroll
    for (int j = 0; j < DCONV; j++) {
        int ls = l - (DCONV - 1) + j;
        if (ls >= 0)
            acc += cw[ch * DCONV + j] * g_xz[(tok0 + ls) * (size_t)(2 * DIN) + ch];
    }
    g_xc[idx] = silu_f(acc);
}

// dt projection -> softplus -> A = -exp(A_log)*dt
__global__ void __launch_bounds__(256)
dtA_kernel(const float* __restrict__ w, const float* __restrict__ dtb,
           const float* __restrict__ Alog)
{
    __shared__ float sw[64][33];
    __shared__ float sx[32][65];
    const int t = threadIdx.x;
    const int tok0 = blockIdx.x * 32;
    const int h = t & 31;
    const int tr = t >> 5;
    float acc[4] = {0.f, 0.f, 0.f, 0.f};
    for (int k0 = 0; k0 < DIN; k0 += 64) {
#pragma unroll
        for (int u = 0; u < 8; u++) {
            int f = t + u * 256;
            sw[f >> 5][f & 31] = w[(size_t)(k0 + (f >> 5)) * NHEADS + (f & 31)];
        }
#pragma unroll
        for (int u = 0; u < 8; u++) {
            int f = t + u * 256;
            sx[f >> 6][f & 63] = g_xc[(size_t)(tok0 + (f >> 6)) * DIN + k0 + (f & 63)];
        }
        __syncthreads();
#pragma unroll
        for (int kk = 0; kk < 64; kk++) {
            float wv = sw[kk][h];
#pragma unroll
            for (int r = 0; r < 4; r++) acc[r] += sx[tr * 4 + r][kk] * wv;
        }
        __syncthreads();
    }
    float na = -__expf(Alog[h]);
    float bh = dtb[h];
#pragma unroll
    for (int r = 0; r < 4; r++) {
        float v = acc[r] + bh;
        float sp = (v > 20.f) ? v : log1pf(__expf(v));
        g_A[(size_t)(tok0 + tr * 4 + r) * NHEADS + h] = na * sp;
    }
}

// ---------------- fused SSD scan (+ Y*silu(z) fusion) ----------------------
__global__ void __launch_bounds__(128)
scan_kernel()
{
    __shared__ float sB[16][68];
    __shared__ float sC[16][68];
    __shared__ float sX[16][36];
    __shared__ float sG[16][16];
    __shared__ float sAv[16];
    __shared__ float sCum[16];
    __shared__ float sPart[16 * 4 * 32];

    const int t = threadIdx.x;
    const int bh = blockIdx.x;
    const int bi = bh >> 5, h = bh & 31;
    const int p0 = blockIdx.y * 32;
    const int p = t & 31;
    const int ng = t >> 5;
    const int i4 = ng * 4;
    const size_t headoff = (size_t)h * HEADDIM;

    float H[16];
#pragma unroll
    for (int i = 0; i < 16; i++) H[i] = 0.f;

    for (int c = 0; c < NCHUNK; c++) {
        const size_t l0 = (size_t)bi * SEQLEN + c * BLK;

#pragma unroll
        for (int u = 0; u < 2; u++) {
            int f = t + u * 128;
            int r = f >> 4, q = (f & 15) * 4;
            const size_t rowBC = (l0 + r) * (size_t)(2 * DIN) + headoff;
            *(float4*)&sB[r][q] = *(const float4*)(g_BC + rowBC + q);
            *(float4*)&sC[r][q] = *(const float4*)(g_BC + rowBC + DIN + q);
        }
        {
            int r = t >> 3, q = (t & 7) * 4;
            *(float4*)&sX[r][q] =
                *(const float4*)(g_xc + (l0 + r) * (size_t)DIN + headoff + p0 + q);
        }
        if (t < 16) sAv[t] = g_A[(l0 + t) * NHEADS + h];
        __syncthreads();

        if (t < 16) {
            float s = 0.f;
            for (int k = 0; k <= t; k++) s += sAv[k];
            sCum[t] = s;
        }
        __syncthreads();
        const float cum15 = sCum[15];

#pragma unroll
        for (int u = 0; u < 2; u++) {
            int e = t + u * 128;
            int i = e >> 4, j = e & 15;
            float gg = 0.f;
            if (j <= i) {
                float d = 0.f;
#pragma unroll
                for (int n = 0; n < 64; n++) d += sC[i][n] * sB[j][n];
                gg = d * __expf(sCum[i] - sCum[j]);
            }
            sG[i][j] = gg;
        }
        {
            int nb = ng * 16;
#pragma unroll
            for (int i = 0; i < 16; i++) {
                float s = 0.f;
#pragma unroll
                for (int k = 0; k < 16; k++) s += sC[i][nb + k] * H[k];
                sPart[(i * 4 + ng) * 32 + p] = s;
            }
        }
        __syncthreads();

        float yv[4];
#pragma unroll
        for (int r = 0; r < 4; r++) {
            int i = i4 + r;
            float s = 0.f;
#pragma unroll
            for (int j = 0; j < 16; j++) s += sG[i][j] * sX[j][p];
            float off = sPart[(i * 4 + 0) * 32 + p] + sPart[(i * 4 + 1) * 32 + p]
                      + sPart[(i * 4 + 2) * 32 + p] + sPart[(i * 4 + 3) * 32 + p];
            yv[r] = s + __expf(sCum[i]) * off;
        }
        __syncthreads();

#pragma unroll
        for (int r = 0; r < 4; r++) {
            int i = i4 + r;
            sX[i][p] *= __expf(cum15 - sCum[i]);
            float zz = g_xz[(l0 + i) * (size_t)(2 * DIN) + DIN + headoff + p0 + p];
            g_Yz[(l0 + i) * (size_t)DIN + headoff + p0 + p] = yv[r] * silu_f(zz);
        }
        __syncthreads();

        {
            float eA = __expf(cum15);
            int nb = ng * 16;
#pragma unroll
            for (int k = 0; k < 16; k++) {
                float s = 0.f;
#pragma unroll
                for (int i = 0; i < 16; i++) s += sB[i][nb + k] * sX[i][p];
                H[k] = eA * H[k] + s;
            }
        }
        __syncthreads();
    }
}

// ---------------- residual + LayerNorm ----------------
__global__ void __launch_bounds__(256)
ln_kernel(const float* __restrict__ res, const float* __restrict__ gamma,
          const float* __restrict__ beta, float* __restrict__ dout)
{
    const int row = blockIdx.x;
    const int t = threadIdx.x;
    const size_t base = (size_t)row * DMODEL;

    float4 r4 = *(const float4*)(res + base + t * 4);
    float4 o4 = *(const float4*)(g_out + base + t * 4);
    float h0 = r4.x + o4.x, h1 = r4.y + o4.y, h2 = r4.z + o4.z, h3 = r4.w + o4.w;
    float s = h0 + h1 + h2 + h3;
    float sq = h0 * h0 + h1 * h1 + h2 * h2 + h3 * h3;

    __shared__ float red[2][8];
#pragma unroll
    for (int o = 16; o > 0; o >>= 1) {
        s += __shfl_xor_sync(0xffffffffu, s, o);
        sq += __shfl_xor_sync(0xffffffffu, sq, o);
    }
    int wid = t >> 5, lid = t & 31;
    if (lid == 0) { red[0][wid] = s; red[1][wid] = sq; }
    __syncthreads();
    if (t < 32) {
        s = (t < 8) ? red[0][t] : 0.f;
        sq = (t < 8) ? red[1][t] : 0.f;
#pragma unroll
        for (int o = 4; o > 0; o >>= 1) {
            s += __shfl_xor_sync(0xffffffffu, s, o);
            sq += __shfl_xor_sync(0xffffffffu, sq, o);
        }
        if (t == 0) { red[0][0] = s; red[1][0] = sq; }
    }
    __syncthreads();
    float mu = red[0][0] * (1.f / DMODEL);
    float var = red[1][0] * (1.f / DMODEL) - mu * mu;
    float inv = rsqrtf(var + 1e-5f);

    float4 g4 = *(const float4*)(gamma + t * 4);
    float4 b4 = *(const float4*)(beta + t * 4);
    float4 ov;
    ov.x = (h0 - mu) * inv * g4.x + b4.x;
    ov.y = (h1 - mu) * inv * g4.y + b4.y;
    ov.z = (h2 - mu) * inv * g4.z + b4.z;
    ov.w = (h3 - mu) * inv * g4.w + b4.w;
    *(float4*)(dout + base + t * 4) = ov;
}

// ---------------- launcher ----------------
extern "C" void kernel_launch(void* const* d_in, const int* in_sizes, int n_in,
                              void* d_out, int out_size)
{
    const float* x        = (const float*)d_in[0];
    const float* ev       = (const float*)d_in[1];
    const float* w_in     = (const float*)d_in[2];   // (1040,4096)
    const float* conv_w   = (const float*)d_in[3];
    const float* conv_b   = (const float*)d_in[4];
    const float* A_log    = (const float*)d_in[5];
    const float* w_B      = (const float*)d_in[6];   // (2048,2048)
    const float* w_C      = (const float*)d_in[7];
    const float* w_dt     = (const float*)d_in[8];
    const float* b_dt     = (const float*)d_in[9];
    const float* w_out    = (const float*)d_in[10];  // (2048,1024)
    const float* ln_gamma = (const float*)d_in[11];
    const float* ln_beta  = (const float*)d_in[12];
    float* out = (float*)d_out;

    cudaFuncSetAttribute(mma_gemm, cudaFuncAttributeMaxDynamicSharedMemorySize, GEMM_SMEM);

    float *p_aug, *p_wint, *p_wbct, *p_wot, *p_xz, *p_xc, *p_BC, *p_Yz, *p_outb;
    cudaGetSymbolAddress((void**)&p_aug,  g_aug);
    cudaGetSymbolAddress((void**)&p_wint, g_wint);
    cudaGetSymbolAddress((void**)&p_wbct, g_wbct);
    cudaGetSymbolAddress((void**)&p_wot,  g_wot);
    cudaGetSymbolAddress((void**)&p_xz,   g_xz);
    cudaGetSymbolAddress((void**)&p_xc,   g_xc);
    cudaGetSymbolAddress((void**)&p_BC,   g_BC);
    cudaGetSymbolAddress((void**)&p_Yz,   g_Yz);
    cudaGetSymbolAddress((void**)&p_outb, g_out);

    // 0) pack + weight transposes
    {
        long long n = (long long)NTOK * KAUG;
        pack_aug_kernel<<<(unsigned)((n + 255) / 256), 256>>>(x, ev);
    }
    transpose_kernel<<<dim3(KAUG / 32, 4096 / 32), 256>>>(w_in, p_wint, 1040, 4096, KAUG);
    transpose_kernel<<<dim3(DIN / 32, DIN / 32), 256>>>(w_B, p_wbct, DIN, DIN, DIN);
    transpose_kernel<<<dim3(DIN / 32, DIN / 32), 256>>>(w_C, p_wbct + (size_t)DIN * DIN,
                                                        DIN, DIN, DIN);
    transpose_kernel<<<dim3(DIN / 32, DMODEL / 32), 256>>>(w_out, p_wot, DIN, DMODEL, DIN);

    // 1) xz = aug @ w_in            (16384 x 4096, K=1056)
    mma_gemm<<<dim3(4096 / BN, NTOK / BM), 256, GEMM_SMEM>>>(p_aug, p_wint, p_xz,
                                                             KAUG, KAUG / GBK, 4096);
    // 2) xc = silu(conv(x_path)+b)
    {
        long long n = (long long)NTOK * DIN;
        conv_silu_kernel<<<(unsigned)((n + 255) / 256), 256>>>(conv_w, conv_b);
    }
    // 3) A
    dtA_kernel<<<NTOK / 32, 256>>>(w_dt, b_dt, A_log);
    // 4) [B|C] = xc @ [w_B|w_C]     (16384 x 4096, K=2048)
    mma_gemm<<<dim3(4096 / BN, NTOK / BM), 256, GEMM_SMEM>>>(p_xc, p_wbct, p_BC,
                                                             DIN, DIN / GBK, 4096);
    // 5) scan -> Yz = Y * silu(z)
    scan_kernel<<<dim3(BATCH * NHEADS, 2), 128>>>();
    // 6) out = Yz @ w_out           (16384 x 1024, K=2048)
    mma_gemm<<<dim3(DMODEL / BN, NTOK / BM), 256, GEMM_SMEM>>>(p_Yz, p_wot, p_outb,
                                                               DIN, DIN / GBK, DMODEL);
    // 7) LayerNorm(residual + out)
    ln_kernel<<<NTOK, 256>>>(x, ln_gamma, ln_beta, out);
}

// round 5
// speedup vs baseline: 3.8629x; 1.7120x over previous
#include <cuda_runtime.h>
#include <cuda_fp16.h>
#include <cstdint>

// ---------------- problem constants ----------------
#define BATCH     4
#define SEQLEN    4096
#define NTOK      (BATCH * SEQLEN)      // 16384
#define DMODEL    1024
#define EVDIM     16
#define DIN       2048                  // d_inner
#define NHEADS    32
#define DSTATE    64
#define HEADDIM   64
#define DCONV     4
#define BLK       16                    // block_len
#define NCHUNK    (SEQLEN / BLK)        // 256
#define KAUG      1088                  // 1040 padded to multiple of 64

// ---------------- scratch (device globals; no runtime allocation) ----------
__device__ __half g_augh [ (size_t)NTOK * KAUG ];    // [x | ev | 0pad] (half)
__device__ __half g_winth[ (size_t)4096 * KAUG ];    // in_proj_w^T (half)
__device__ __half g_wbcth[ (size_t)4096 * DIN ];     // [w_B^T ; w_C^T] (half)
__device__ __half g_woth [ (size_t)DMODEL * DIN ];   // out_proj_w^T (half)
__device__ __half g_xch  [ (size_t)NTOK * DIN ];     // xc as half (GEMM operand)
__device__ __half g_Yzh  [ (size_t)NTOK * DIN ];     // Y*silu(z) as half
__device__ float  g_xz   [ (size_t)NTOK * 2 * DIN ]; // x_path | z (f32)
__device__ float  g_xc   [ (size_t)NTOK * DIN ];     // conv+silu out (f32)
__device__ float  g_A    [ (size_t)NTOK * NHEADS ];
__device__ float  g_BC   [ (size_t)NTOK * 2 * DIN ]; // [B | C] per row (f32)
__device__ float  g_out  [ (size_t)NTOK * DMODEL ];  // pre-LN (f32)

// ================= helpers =================================================
__device__ __forceinline__ uint32_t smem_u32(const void* p) {
    uint32_t a;
    asm("{ .reg .u64 t; cvta.to.shared.u64 t, %1; cvt.u32.u64 %0, t; }"
        : "=r"(a) : "l"(p));
    return a;
}
__device__ __forceinline__ void cp16(uint32_t s, const void* g) {
    asm volatile("cp.async.cg.shared.global [%0], [%1], 16;\n" :: "r"(s), "l"(g));
}
__device__ __forceinline__ void cp4(uint32_t s, const void* g) {
    asm volatile("cp.async.ca.shared.global [%0], [%1], 4;\n" :: "r"(s), "l"(g));
}
__device__ __forceinline__ void cp_commit() { asm volatile("cp.async.commit_group;\n" ::); }
template<int N> __device__ __forceinline__ void cp_wait() {
    asm volatile("cp.async.wait_group %0;\n" :: "n"(N));
}
__device__ __forceinline__ void mma16(float* c, const uint32_t* a, const uint32_t* b) {
    asm volatile(
        "mma.sync.aligned.m16n8k16.row.col.f32.f16.f16.f32 "
        "{%0,%1,%2,%3}, {%4,%5,%6,%7}, {%8,%9}, {%0,%1,%2,%3};"
        : "+f"(c[0]), "+f"(c[1]), "+f"(c[2]), "+f"(c[3])
        : "r"(a[0]), "r"(a[1]), "r"(a[2]), "r"(a[3]), "r"(b[0]), "r"(b[1]));
}
__device__ __forceinline__ float silu_f(float z) { return z / (1.f + __expf(-z)); }

// ================= fp16 warp-MMA GEMM ======================================
// C[M,Ncols] (f32, row-major) = A[M,Kp] @ Bt[Ncols,Kp]^T, both half K-major.
// Block tile 128x128xK64, 8 warps (2Mx4N), warp tile 64x32, m16n8k16.
#define BM 128
#define BN 128
#define GBK 64
#define KPADH 72                          // padded row stride in halves
#define A_ST_H (BM * KPADH)               // 9216 halves per operand per stage
#define STAGE_B (2 * A_ST_H * 2)          // 36864 bytes per stage
#define GEMM_SMEM (2 * STAGE_B)           // 73728 bytes

__global__ void __launch_bounds__(256, 2)
mma_gemm(const __half* __restrict__ A, const __half* __restrict__ Bt,
         float* __restrict__ C, int Kp, int NKB, int Ncols)
{
    extern __shared__ __half smh[];
    const uint32_t sbase = smem_u32(smh);
    const int tid  = threadIdx.x;
    const int lane = tid & 31, wid = tid >> 5;
    const int mwarp = wid & 1, nwarp = wid >> 1;      // 2 x 4 warp grid
    const int g = lane >> 2, tig = lane & 3;
    const int row0 = blockIdx.y * BM, col0 = blockIdx.x * BN;

    float acc[4][4][4];
#pragma unroll
    for (int mi = 0; mi < 4; mi++)
#pragma unroll
        for (int ni = 0; ni < 4; ni++)
#pragma unroll
            for (int r = 0; r < 4; r++) acc[mi][ni][r] = 0.f;

    auto fill = [&](int kb, int s) {
        const uint32_t ab = sbase + (uint32_t)s * STAGE_B;
        const uint32_t bb = ab + A_ST_H * 2;
        const int k0 = kb * GBK;
#pragma unroll
        for (int u = 0; u < 4; u++) {
            int c = tid + u * 256;                    // 0..1023 chunks
            int r = c >> 3, q = c & 7;                // row, 16B chunk (8 halves)
            cp16(ab + r * (KPADH * 2) + q * 16,
                 A + (size_t)(row0 + r) * Kp + k0 + q * 8);
            cp16(bb + r * (KPADH * 2) + q * 16,
                 Bt + (size_t)(col0 + r) * Kp + k0 + q * 8);
        }
        cp_commit();
    };

    fill(0, 0);
    if (NKB > 1) fill(1, 1);
    for (int kb = 0; kb < NKB; kb++) {
        if (kb + 2 < NKB) { cp_wait<2>(); } // not needed; keep simple below
        if (kb + 1 < NKB) cp_wait<1>(); else cp_wait<0>();
        __syncthreads();

        const __half* Ah = smh + (kb & 1) * (STAGE_B / 2);
        const __half* Bh = Ah + A_ST_H;
#pragma unroll
        for (int kk = 0; kk < 4; kk++) {
            const int kb2 = kk * 16;
            uint32_t af[4][4], bf[4][2];
#pragma unroll
            for (int mi = 0; mi < 4; mi++) {
                const __half* ap = Ah + (mwarp * 64 + mi * 16 + g) * KPADH + kb2 + 2 * tig;
                af[mi][0] = *(const uint32_t*)(ap);
                af[mi][1] = *(const uint32_t*)(ap + 8 * KPADH);
                af[mi][2] = *(const uint32_t*)(ap + 8);
                af[mi][3] = *(const uint32_t*)(ap + 8 * KPADH + 8);
            }
#pragma unroll
            for (int ni = 0; ni < 4; ni++) {
                const __half* bp = Bh + (nwarp * 32 + ni * 8 + g) * KPADH + kb2 + 2 * tig;
                bf[ni][0] = *(const uint32_t*)(bp);
                bf[ni][1] = *(const uint32_t*)(bp + 8);
            }
#pragma unroll
            for (int mi = 0; mi < 4; mi++)
#pragma unroll
                for (int ni = 0; ni < 4; ni++)
                    mma16(acc[mi][ni], af[mi], bf[ni]);
        }
        __syncthreads();
        if (kb + 2 < NKB) fill(kb + 2, kb & 1);
    }

    // ---- epilogue: direct f32 global stores
#pragma unroll
    for (int mi = 0; mi < 4; mi++) {
        const int r0 = row0 + mwarp * 64 + mi * 16 + g;
#pragma unroll
        for (int ni = 0; ni < 4; ni++) {
            const int cc = col0 + nwarp * 32 + ni * 8 + 2 * tig;
            *(float2*)(C + (size_t)r0 * Ncols + cc) =
                make_float2(acc[mi][ni][0], acc[mi][ni][1]);
            *(float2*)(C + (size_t)(r0 + 8) * Ncols + cc) =
                make_float2(acc[mi][ni][2], acc[mi][ni][3]);
        }
    }
}

// ================= pre/post processing =====================================
__global__ void __launch_bounds__(256)
pack_aug_kernel(const float* __restrict__ x, const float* __restrict__ ev)
{
    long long idx = (long long)blockIdx.x * blockDim.x + threadIdx.x;
    if (idx >= (long long)NTOK * KAUG) return;
    int col = (int)(idx % KAUG);
    long long m = idx / KAUG;
    float v;
    if (col < DMODEL)              v = x[m * DMODEL + col];
    else if (col < DMODEL + EVDIM) v = ev[m * EVDIM + (col - DMODEL)];
    else                           v = 0.f;
    g_augh[idx] = __float2half_rn(v);
}

// dst[n][kp] = (kp < K) ? src[kp*N + n] : 0  (f32 -> half)
__global__ void __launch_bounds__(256)
transpose_kernel(const float* __restrict__ src, __half* __restrict__ dst,
                 int K, int N, int Kp)
{
    __shared__ float tile[32][33];
    const int tx = threadIdx.x & 31, ty = threadIdx.x >> 5;
    const int kb = blockIdx.x * 32, nb = blockIdx.y * 32;
#pragma unroll
    for (int u = 0; u < 4; u++) {
        int kk = kb + ty + u * 8;
        tile[ty + u * 8][tx] = (kk < K) ? src[(size_t)kk * N + nb + tx] : 0.f;
    }
    __syncthreads();
#pragma unroll
    for (int u = 0; u < 4; u++) {
        int n = nb + ty + u * 8;
        dst[(size_t)n * Kp + kb + tx] = __float2half_rn(tile[tx][ty + u * 8]);
    }
}

// causal depthwise conv (d_conv=4) + SiLU; writes f32 + half copies
__global__ void __launch_bounds__(256)
conv_silu_kernel(const float* __restrict__ cw, const float* __restrict__ cb)
{
    long long idx = (long long)blockIdx.x * blockDim.x + threadIdx.x;
    if (idx >= (long long)NTOK * DIN) return;
    int ch = (int)(idx & (DIN - 1));
    long long tok = idx >> 11;
    int l = (int)(tok & (SEQLEN - 1));
    long long tok0 = tok - l;
    float acc = cb[ch];
#pragma unroll
    for (int j = 0; j < DCONV; j++) {
        int ls = l - (DCONV - 1) + j;
        if (ls >= 0)
            acc += cw[ch * DCONV + j] * g_xz[(tok0 + ls) * (size_t)(2 * DIN) + ch];
    }
    float v = silu_f(acc);
    g_xc[idx] = v;
    g_xch[idx] = __float2half_rn(v);
}

// dt projection -> softplus -> A = -exp(A_log)*dt
__global__ void __launch_bounds__(256)
dtA_kernel(const float* __restrict__ w, const float* __restrict__ dtb,
           const float* __restrict__ Alog)
{
    __shared__ float sw[64][33];
    __shared__ float sx[32][65];
    const int t = threadIdx.x;
    const int tok0 = blockIdx.x * 32;
    const int h = t & 31;
    const int tr = t >> 5;
    float acc[4] = {0.f, 0.f, 0.f, 0.f};
    for (int k0 = 0; k0 < DIN; k0 += 64) {
#pragma unroll
        for (int u = 0; u < 8; u++) {
            int f = t + u * 256;
            sw[f >> 5][f & 31] = w[(size_t)(k0 + (f >> 5)) * NHEADS + (f & 31)];
        }
#pragma unroll
        for (int u = 0; u < 8; u++) {
            int f = t + u * 256;
            sx[f >> 6][f & 63] = g_xc[(size_t)(tok0 + (f >> 6)) * DIN + k0 + (f & 63)];
        }
        __syncthreads();
#pragma unroll
        for (int kk = 0; kk < 64; kk++) {
            float wv = sw[kk][h];
#pragma unroll
            for (int r = 0; r < 4; r++) acc[r] += sx[tr * 4 + r][kk] * wv;
        }
        __syncthreads();
    }
    float na = -__expf(Alog[h]);
    float bh = dtb[h];
#pragma unroll
    for (int r = 0; r < 4; r++) {
        float v = acc[r] + bh;
        float sp = (v > 20.f) ? v : log1pf(__expf(v));
        g_A[(size_t)(tok0 + tr * 4 + r) * NHEADS + h] = na * sp;
    }
}

// ---------------- fused SSD scan (double-buffered cp.async prefetch) -------
__global__ void __launch_bounds__(128)
scan_kernel()
{
    __shared__ float sB[2][16][68];
    __shared__ float sC[2][16][68];
    __shared__ float sX[2][16][36];
    __shared__ float sAv[2][16];
    __shared__ float sG[16][16];
    __shared__ float sCum[16];
    __shared__ float sPart[16 * 4 * 32];

    const int t = threadIdx.x;
    const int bh = blockIdx.x;
    const int bi = bh >> 5, h = bh & 31;
    const int p0 = blockIdx.y * 32;
    const int p = t & 31;
    const int ng = t >> 5;
    const int i4 = ng * 4;
    const size_t headoff = (size_t)h * HEADDIM;

    const uint32_t uB = smem_u32(sB), uC = smem_u32(sC);
    const uint32_t uX = smem_u32(sX), uA = smem_u32(sAv);

    auto loadChunk = [&](int c, int st) {
        const size_t l0 = (size_t)bi * SEQLEN + c * BLK;
#pragma unroll
        for (int u = 0; u < 2; u++) {
            int f = t + u * 128;
            int r = f >> 4, q = f & 15;               // row, 16B chunk
            const size_t rowBC = (l0 + r) * (size_t)(2 * DIN) + headoff;
            uint32_t so = (uint32_t)(((st * 16 + r) * 68 + q * 4) * 4);
            cp16(uB + so, g_BC + rowBC + q * 4);
            cp16(uC + so, g_BC + rowBC + DIN + q * 4);
        }
        {
            int r = t >> 3, q = t & 7;
            uint32_t so = (uint32_t)(((st * 16 + r) * 36 + q * 4) * 4);
            cp16(uX + so, g_xc + (l0 + r) * (size_t)DIN + headoff + p0 + q * 4);
        }
        if (t < 16)
            cp4(uA + (uint32_t)((st * 16 + t) * 4), g_A + (l0 + t) * NHEADS + h);
        cp_commit();
    };

    float H[16];
#pragma unroll
    for (int i = 0; i < 16; i++) H[i] = 0.f;

    loadChunk(0, 0);
    for (int c = 0; c < NCHUNK; c++) {
        const int st = c & 1;
        if (c + 1 < NCHUNK) { loadChunk(c + 1, st ^ 1); cp_wait<1>(); }
        else                { cp_wait<0>(); }
        __syncthreads();

        const size_t l0 = (size_t)bi * SEQLEN + c * BLK;

        if (t < 16) {
            float s = 0.f;
            for (int k = 0; k <= t; k++) s += sAv[st][k];
            sCum[t] = s;
        }
        __syncthreads();
        const float cum15 = sCum[15];

#pragma unroll
        for (int u = 0; u < 2; u++) {
            int e = t + u * 128;
            int i = e >> 4, j = e & 15;
            float gg = 0.f;
            if (j <= i) {
                float d = 0.f;
#pragma unroll
                for (int n = 0; n < 64; n++) d += sC[st][i][n] * sB[st][j][n];
                gg = d * __expf(sCum[i] - sCum[j]);
            }
            sG[i][j] = gg;
        }
        {
            int nb = ng * 16;
#pragma unroll
            for (int i = 0; i < 16; i++) {
                float s = 0.f;
#pragma unroll
                for (int k = 0; k < 16; k++) s += sC[st][i][nb + k] * H[k];
                sPart[(i * 4 + ng) * 32 + p] = s;
            }
        }
        __syncthreads();

        float yv[4];
#pragma unroll
        for (int r = 0; r < 4; r++) {
            int i = i4 + r;
            float s = 0.f;
#pragma unroll
            for (int j = 0; j < 16; j++) s += sG[i][j] * sX[st][j][p];
            float off = sPart[(i * 4 + 0) * 32 + p] + sPart[(i * 4 + 1) * 32 + p]
                      + sPart[(i * 4 + 2) * 32 + p] + sPart[(i * 4 + 3) * 32 + p];
            yv[r] = s + __expf(sCum[i]) * off;
        }
        __syncthreads();

#pragma unroll
        for (int r = 0; r < 4; r++) {
            int i = i4 + r;
            sX[st][i][p] *= __expf(cum15 - sCum[i]);
            float zz = g_xz[(l0 + i) * (size_t)(2 * DIN) + DIN + headoff + p0 + p];
            g_Yzh[(l0 + i) * (size_t)DIN + headoff + p0 + p] =
                __float2half_rn(yv[r] * silu_f(zz));
        }
        __syncthreads();

        {
            float eA = __expf(cum15);
            int nb = ng * 16;
#pragma unroll
            for (int k = 0; k < 16; k++) {
                float s = 0.f;
#pragma unroll
                for (int i = 0; i < 16; i++) s += sB[st][i][nb + k] * sX[st][i][p];
                H[k] = eA * H[k] + s;
            }
        }
        __syncthreads();
    }
}

// ---------------- residual + LayerNorm ----------------
__global__ void __launch_bounds__(256)
ln_kernel(const float* __restrict__ res, const float* __restrict__ gamma,
          const float* __restrict__ beta, float* __restrict__ dout)
{
    const int row = blockIdx.x;
    const int t = threadIdx.x;
    const size_t base = (size_t)row * DMODEL;

    float4 r4 = *(const float4*)(res + base + t * 4);
    float4 o4 = *(const float4*)(g_out + base + t * 4);
    float h0 = r4.x + o4.x, h1 = r4.y + o4.y, h2 = r4.z + o4.z, h3 = r4.w + o4.w;
    float s = h0 + h1 + h2 + h3;
    float sq = h0 * h0 + h1 * h1 + h2 * h2 + h3 * h3;

    __shared__ float red[2][8];
#pragma unroll
    for (int o = 16; o > 0; o >>= 1) {
        s += __shfl_xor_sync(0xffffffffu, s, o);
        sq += __shfl_xor_sync(0xffffffffu, sq, o);
    }
    int wid = t >> 5, lid = t & 31;
    if (lid == 0) { red[0][wid] = s; red[1][wid] = sq; }
    __syncthreads();
    if (t < 32) {
        s = (t < 8) ? red[0][t] : 0.f;
        sq = (t < 8) ? red[1][t] : 0.f;
#pragma unroll
        for (int o = 4; o > 0; o >>= 1) {
            s += __shfl_xor_sync(0xffffffffu, s, o);
            sq += __shfl_xor_sync(0xffffffffu, sq, o);
        }
        if (t == 0) { red[0][0] = s; red[1][0] = sq; }
    }
    __syncthreads();
    float mu = red[0][0] * (1.f / DMODEL);
    float var = red[1][0] * (1.f / DMODEL) - mu * mu;
    float inv = rsqrtf(var + 1e-5f);

    float4 g4 = *(const float4*)(gamma + t * 4);
    float4 b4 = *(const float4*)(beta + t * 4);
    float4 ov;
    ov.x = (h0 - mu) * inv * g4.x + b4.x;
    ov.y = (h1 - mu) * inv * g4.y + b4.y;
    ov.z = (h2 - mu) * inv * g4.z + b4.z;
    ov.w = (h3 - mu) * inv * g4.w + b4.w;
    *(float4*)(dout + base + t * 4) = ov;
}

// ---------------- launcher ----------------
extern "C" void kernel_launch(void* const* d_in, const int* in_sizes, int n_in,
                              void* d_out, int out_size)
{
    const float* x        = (const float*)d_in[0];
    const float* ev       = (const float*)d_in[1];
    const float* w_in     = (const float*)d_in[2];   // (1040,4096)
    const float* conv_w   = (const float*)d_in[3];
    const float* conv_b   = (const float*)d_in[4];
    const float* A_log    = (const float*)d_in[5];
    const float* w_B      = (const float*)d_in[6];   // (2048,2048)
    const float* w_C      = (const float*)d_in[7];
    const float* w_dt     = (const float*)d_in[8];
    const float* b_dt     = (const float*)d_in[9];
    const float* w_out    = (const float*)d_in[10];  // (2048,1024)
    const float* ln_gamma = (const float*)d_in[11];
    const float* ln_beta  = (const float*)d_in[12];
    float* out = (float*)d_out;

    cudaFuncSetAttribute(mma_gemm, cudaFuncAttributeMaxDynamicSharedMemorySize, GEMM_SMEM);

    __half *p_augh, *p_winth, *p_wbcth, *p_woth, *p_xch, *p_Yzh;
    float *p_xz, *p_BC, *p_outb;
    cudaGetSymbolAddress((void**)&p_augh,  g_augh);
    cudaGetSymbolAddress((void**)&p_winth, g_winth);
    cudaGetSymbolAddress((void**)&p_wbcth, g_wbcth);
    cudaGetSymbolAddress((void**)&p_woth,  g_woth);
    cudaGetSymbolAddress((void**)&p_xch,   g_xch);
    cudaGetSymbolAddress((void**)&p_Yzh,   g_Yzh);
    cudaGetSymbolAddress((void**)&p_xz,    g_xz);
    cudaGetSymbolAddress((void**)&p_BC,    g_BC);
    cudaGetSymbolAddress((void**)&p_outb,  g_out);

    // 0) pack + weight transposes (f32 -> half)
    {
        long long n = (long long)NTOK * KAUG;
        pack_aug_kernel<<<(unsigned)((n + 255) / 256), 256>>>(x, ev);
    }
    transpose_kernel<<<dim3(KAUG / 32, 4096 / 32), 256>>>(w_in, p_winth, 1040, 4096, KAUG);
    transpose_kernel<<<dim3(DIN / 32, DIN / 32), 256>>>(w_B, p_wbcth, DIN, DIN, DIN);
    transpose_kernel<<<dim3(DIN / 32, DIN / 32), 256>>>(w_C, p_wbcth + (size_t)DIN * DIN,
                                                        DIN, DIN, DIN);
    transpose_kernel<<<dim3(DIN / 32, DMODEL / 32), 256>>>(w_out, p_woth, DIN, DMODEL, DIN);

    // 1) xz = aug @ w_in            (16384 x 4096, K=1088)
    mma_gemm<<<dim3(4096 / BN, NTOK / BM), 256, GEMM_SMEM>>>(p_augh, p_winth, p_xz,
                                                             KAUG, KAUG / GBK, 4096);
    // 2) xc = silu(conv(x_path)+b)
    {
        long long n = (long long)NTOK * DIN;
        conv_silu_kernel<<<(unsigned)((n + 255) / 256), 256>>>(conv_w, conv_b);
    }
    // 3) A
    dtA_kernel<<<NTOK / 32, 256>>>(w_dt, b_dt, A_log);
    // 4) [B|C] = xc @ [w_B|w_C]     (16384 x 4096, K=2048)
    mma_gemm<<<dim3(4096 / BN, NTOK / BM), 256, GEMM_SMEM>>>(p_xch, p_wbcth, p_BC,
                                                             DIN, DIN / GBK, 4096);
    // 5) scan -> Yz (half)
    scan_kernel<<<dim3(BATCH * NHEADS, 2), 128>>>();
    // 6) out = Yz @ w_out           (16384 x 1024, K=2048)
    mma_gemm<<<dim3(DMODEL / BN, NTOK / BM), 256, GEMM_SMEM>>>(p_Yzh, p_woth, p_outb,
                                                               DIN, DIN / GBK, DMODEL);
    // 7) LayerNorm(residual + out)
    ln_kernel<<<NTOK, 256>>>(x, ln_gamma, ln_beta, out);
}